// round 1
// baseline (speedup 1.0000x reference)
#include <cuda_runtime.h>

// AdderConv + BatchNorm2d (training stats) for x[8,32,28,28], W[64,32,3,3], pad=1.
// out[n,o,h,w] = -sum_{c,r,s} |x[n,c,h+r-1,w+s-1] - W[o,c,r,s]|  (zero padding)
// then per-channel BN over (N,H,W) with biased variance, eps=1e-5.

__device__ __forceinline__ unsigned long long add_f32x2(unsigned long long a,
                                                        unsigned long long b) {
    unsigned long long r;
    asm("add.rn.f32x2 %0, %1, %2;" : "=l"(r) : "l"(a), "l"(b));
    return r;
}

// Kernel 1: adder conv.
// grid: (4 spatial tiles 14x14, 8 oc-groups of 8, 8 batch), block: 256 threads.
// smem: x tile 32ch x 16x16 (halo'd) = 32KB, negated W slice k-major [288][8] = 9KB.
__global__ __launch_bounds__(256, 1) void adder_kernel(
    const float* __restrict__ x, const float* __restrict__ W, float* __restrict__ out)
{
    __shared__ __align__(16) float xs[32 * 16 * 16];
    __shared__ __align__(16) float nws[288 * 8];

    const int s   = blockIdx.x;   // spatial tile 0..3
    const int ocg = blockIdx.y;   // 0..7 (8 output channels each)
    const int n   = blockIdx.z;   // 0..7
    const int th  = (s >> 1) * 14;
    const int tw  = (s & 1) * 14;
    const int tid = threadIdx.x;

    // Load x tile (with zero halo for padding).
    const float* xb = x + n * (32 * 28 * 28);
    #pragma unroll
    for (int i = tid; i < 32 * 256; i += 256) {
        int c = i >> 8, cell = i & 255;
        int r = cell >> 4, col = cell & 15;
        int gh = th - 1 + r, gw = tw - 1 + col;
        float v = 0.f;
        if ((unsigned)gh < 28u && (unsigned)gw < 28u)
            v = xb[c * 784 + gh * 28 + gw];
        xs[i] = v;
    }
    // Load negated W slice, k-major so 8 oc values are contiguous per k.
    const float* Wb = W + ocg * (8 * 288);
    #pragma unroll
    for (int i = tid; i < 8 * 288; i += 256) {
        int o = i & 7, k = i >> 3;
        nws[k * 8 + o] = -Wb[o * 288 + k];
    }
    __syncthreads();

    if (tid < 196) {
        const int ph = tid / 14;
        const int pw = tid - ph * 14;
        unsigned long long acc0 = 0ull, acc1 = 0ull, acc2 = 0ull, acc3 = 0ull;
        const float* xp = xs + ph * 16 + pw;
        const ulonglong2* wp = (const ulonglong2*)nws;

        #pragma unroll 1
        for (int c = 0; c < 32; ++c) {
            const float* xc = xp + c * 256;
            #pragma unroll
            for (int r = 0; r < 3; ++r) {
                #pragma unroll
                for (int q = 0; q < 3; ++q) {
                    float xv = xc[r * 16 + q];
                    unsigned long long xx;
                    asm("mov.b64 %0, {%1, %1};" : "=l"(xx) : "r"(__float_as_uint(xv)));
                    const ulonglong2* w4 = wp + (c * 9 + r * 3 + q) * 2;
                    ulonglong2 wA = w4[0];
                    ulonglong2 wB = w4[1];
                    // diff = x + (-w) packed over 2 oc; abs via sign-mask (ALU pipe)
                    unsigned long long d0 = add_f32x2(xx, wA.x) & 0x7FFFFFFF7FFFFFFFULL;
                    unsigned long long d1 = add_f32x2(xx, wA.y) & 0x7FFFFFFF7FFFFFFFULL;
                    unsigned long long d2 = add_f32x2(xx, wB.x) & 0x7FFFFFFF7FFFFFFFULL;
                    unsigned long long d3 = add_f32x2(xx, wB.y) & 0x7FFFFFFF7FFFFFFFULL;
                    acc0 = add_f32x2(acc0, d0);
                    acc1 = add_f32x2(acc1, d1);
                    acc2 = add_f32x2(acc2, d2);
                    acc3 = add_f32x2(acc3, d3);
                }
            }
        }

        const int gh = th + ph, gw = tw + pw;
        float* ob = out + (n * 64 + ocg * 8) * 784 + gh * 28 + gw;
        unsigned long long a[4] = {acc0, acc1, acc2, acc3};
        #pragma unroll
        for (int j = 0; j < 4; ++j) {
            ob[(2 * j) * 784]     = -__uint_as_float((unsigned)(a[j] & 0xFFFFFFFFu));
            ob[(2 * j + 1) * 784] = -__uint_as_float((unsigned)(a[j] >> 32));
        }
    }
}

// Kernel 2: per-channel BN (training mode, biased var), in-place on out.
// grid: 64 blocks (one per channel), block: 256 threads. Deterministic tree reduce.
__global__ __launch_bounds__(256, 1) void bn_kernel(
    float* __restrict__ out, const float* __restrict__ gamma, const float* __restrict__ beta)
{
    const int o = blockIdx.x;
    const int tid = threadIdx.x;

    float s = 0.f, sq = 0.f;
    for (int i = tid; i < 6272; i += 256) {
        int n = i / 784;
        int hw = i - n * 784;
        float v = out[(n * 64 + o) * 784 + hw];
        s += v;
        sq += v * v;
    }

    __shared__ float rs[256], rq[256];
    rs[tid] = s; rq[tid] = sq;
    __syncthreads();
    #pragma unroll
    for (int st = 128; st > 0; st >>= 1) {
        if (tid < st) { rs[tid] += rs[tid + st]; rq[tid] += rq[tid + st]; }
        __syncthreads();
    }

    __shared__ float sc_s, bi_s;
    if (tid == 0) {
        float mean = rs[0] * (1.f / 6272.f);
        float var  = rq[0] * (1.f / 6272.f) - mean * mean;
        float sc = gamma[o] * rsqrtf(var + 1e-5f);
        sc_s = sc;
        bi_s = beta[o] - mean * sc;
    }
    __syncthreads();

    float sc = sc_s, bi = bi_s;
    for (int i = tid; i < 6272; i += 256) {
        int n = i / 784;
        int hw = i - n * 784;
        int idx = (n * 64 + o) * 784 + hw;
        out[idx] = out[idx] * sc + bi;
    }
}

extern "C" void kernel_launch(void* const* d_in, const int* in_sizes, int n_in,
                              void* d_out, int out_size) {
    const float* x     = (const float*)d_in[0];  // [8,32,28,28]
    const float* W     = (const float*)d_in[1];  // [64,32,3,3]
    const float* gamma = (const float*)d_in[2];  // [64]
    const float* beta  = (const float*)d_in[3];  // [64]
    float* out = (float*)d_out;                  // [8,64,28,28]

    dim3 g1(4, 8, 8);
    adder_kernel<<<g1, 256>>>(x, W, out);
    bn_kernel<<<64, 256>>>(out, gamma, beta);
}